// round 16
// baseline (speedup 1.0000x reference)
#include <cuda_runtime.h>
#include <cuda_fp16.h>
#include <cstdint>

#define BATCH 4
#define CHN   256
#define NTOK  4096
#define EPS   1e-5f

typedef __half h16;

// ------------------------------------------------------------------
// scratch (__device__ globals; no allocations allowed)
// ------------------------------------------------------------------
__device__ h16 g_xn[(size_t)BATCH*NTOK*CHN];      // groupnormed x [b][n][c]
__device__ int8_t g_qi[(size_t)BATCH*NTOK*CHN];   // Q int8 [b][n][c], scale 4/127
__device__ int8_t g_ki[(size_t)BATCH*NTOK*CHN];   // K int8 [b][m][c]
__device__ h16 g_v [(size_t)BATCH*CHN*NTOK];      // V [b][c][m]
__device__ h16 g_s [(size_t)BATCH*NTOK*NTOK];     // exp-scores fp16 [b][n][m]
__device__ h16 g_ao[(size_t)BATCH*NTOK*CHN];      // attn-out (normalized) [b][n][c]
__device__ float g_rsum[(size_t)BATCH*NTOK*32];   // per-key-block row sums
__device__ float g_rinv[(size_t)BATCH*NTOK];      // 1 / total row sum
__device__ h16 g_wq[3*CHN*CHN];
__device__ h16 g_wo[CHN*CHN];

// ------------------------------------------------------------------
__device__ __forceinline__ uint32_t smem_u32(const void* p) {
    uint32_t a;
    asm("{ .reg .u64 t; cvta.to.shared.u64 t, %1; cvt.u32.u64 %0, t; }" : "=r"(a) : "l"(p));
    return a;
}
__device__ __forceinline__ void ldsm_x4(uint32_t& r0, uint32_t& r1, uint32_t& r2,
                                        uint32_t& r3, uint32_t addr) {
    asm volatile("ldmatrix.sync.aligned.m8n8.x4.shared.b16 {%0,%1,%2,%3}, [%4];"
                 : "=r"(r0), "=r"(r1), "=r"(r2), "=r"(r3) : "r"(addr));
}
__device__ __forceinline__ void mma_f16(float* c, uint32_t a0, uint32_t a1,
                                        uint32_t a2, uint32_t a3,
                                        uint32_t b0, uint32_t b1) {
    asm volatile("mma.sync.aligned.m16n8k16.row.col.f32.f16.f16.f32 "
                 "{%0,%1,%2,%3}, {%4,%5,%6,%7}, {%8,%9}, {%0,%1,%2,%3};"
                 : "+f"(c[0]), "+f"(c[1]), "+f"(c[2]), "+f"(c[3])
                 : "r"(a0), "r"(a1), "r"(a2), "r"(a3), "r"(b0), "r"(b1));
}
__device__ __forceinline__ void mma_s8(int32_t* c, uint32_t a0, uint32_t a1,
                                       uint32_t a2, uint32_t a3,
                                       uint32_t b0, uint32_t b1) {
    asm volatile("mma.sync.aligned.m16n8k32.row.col.s32.s8.s8.s32 "
                 "{%0,%1,%2,%3}, {%4,%5,%6,%7}, {%8,%9}, {%0,%1,%2,%3};"
                 : "+r"(c[0]), "+r"(c[1]), "+r"(c[2]), "+r"(c[3])
                 : "r"(a0), "r"(a1), "r"(a2), "r"(a3), "r"(b0), "r"(b1));
}
__device__ __forceinline__ void cpasync16(uint32_t dst, const void* src) {
    asm volatile("cp.async.cg.shared.global [%0], [%1], 16;" :: "r"(dst), "l"(src));
}
#define CP_COMMIT() asm volatile("cp.async.commit_group;" ::: "memory")
#define CP_WAIT2()  asm volatile("cp.async.wait_group 2;" ::: "memory")
#define CP_WAIT1()  asm volatile("cp.async.wait_group 1;" ::: "memory")
#define CP_WAIT0()  asm volatile("cp.async.wait_group 0;" ::: "memory")

__device__ __forceinline__ uint32_t pk2(h16 a, h16 b) {
    __half2 t; t.x = a; t.y = b;
    return *reinterpret_cast<uint32_t*>(&t);
}
__device__ __forceinline__ uint32_t ex2_h2(float t0, float t1) {
    __half2 h = __floats2half2_rn(t0, t1);
    uint32_t in = *reinterpret_cast<uint32_t*>(&h), out;
    asm("ex2.approx.f16x2 %0, %1;" : "=r"(out) : "r"(in));
    return out;
}
__device__ __forceinline__ uint32_t q8(float v0, float v1, float v2, float v3) {
    // clamp +-3.999, scale 127/4, round, pack 4 int8
    int i0 = __float2int_rn(fminf(fmaxf(v0, -3.999f), 3.999f) * 31.75f);
    int i1 = __float2int_rn(fminf(fmaxf(v1, -3.999f), 3.999f) * 31.75f);
    int i2 = __float2int_rn(fminf(fmaxf(v2, -3.999f), 3.999f) * 31.75f);
    int i3 = __float2int_rn(fminf(fmaxf(v3, -3.999f), 3.999f) * 31.75f);
    return (uint32_t)(i0 & 255) | ((uint32_t)(i1 & 255) << 8) |
           ((uint32_t)(i2 & 255) << 16) | ((uint32_t)(i3 & 255) << 24);
}

// fp16 path smem: 3 stages x (A[128][40] + B[128][40]) h16 = 61440, union stg [128][132]f
#define TPAD 40
#define SPAD 132
#define STAGE_BYTES 20480
#define SMEM_BYTES  (128 * SPAD * 4)   // 67584
// int8 scores smem: 3 stages x (A[128][48B] + B[128][48B]) = 36864
#define TP8 48
#define STAGE8 12288
#define SMEM_I8 36864

// exp(s/16 - 6) = 2^(s*EC1 + EC2); int8 dequant folded: SCL = (4/127)^2/16*log2e
#define EC1 0.09016844005556021f
#define EC2 -8.65617024533378f
#define SCL 8.94474986e-5f

// ------------------------------------------------------------------
// GroupNorm -> fp16 token-major [b][n][c]
// ------------------------------------------------------------------
__global__ __launch_bounds__(256) void gn_kernel(const float* __restrict__ x,
                                                 const float* __restrict__ w,
                                                 const float* __restrict__ bias) {
    int b = blockIdx.x >> 5;
    int g = blockIdx.x & 31;
    size_t base = ((size_t)b * CHN + g * 8) * NTOK;
    const float4* xv = (const float4*)(x + base);
    const int NV = 8 * NTOK / 4;

    float s = 0.f, ss = 0.f;
    for (int i = threadIdx.x; i < NV; i += 256) {
        float4 v = xv[i];
        s  += v.x + v.y + v.z + v.w;
        ss += v.x*v.x + v.y*v.y + v.z*v.z + v.w*v.w;
    }
    __shared__ float rs[256], rss[256];
    rs[threadIdx.x] = s; rss[threadIdx.x] = ss;
    __syncthreads();
    for (int st = 128; st > 0; st >>= 1) {
        if (threadIdx.x < st) { rs[threadIdx.x] += rs[threadIdx.x+st]; rss[threadIdx.x] += rss[threadIdx.x+st]; }
        __syncthreads();
    }
    float mean = rs[0] * (1.f/32768.f);
    float var  = rss[0] * (1.f/32768.f) - mean*mean;
    float rstd = rsqrtf(var + EPS);

    float sc[8], sh[8];
    #pragma unroll
    for (int c = 0; c < 8; c++) {
        sc[c] = w[g*8+c] * rstd;
        sh[c] = bias[g*8+c] - mean * sc[c];
    }
    for (int it = 0; it < 16; it++) {
        int n = it * 256 + threadIdx.x;
        uint32_t hp[4];
        #pragma unroll
        for (int p = 0; p < 4; p++) {
            float v0 = x[base + (size_t)(2*p  )*NTOK + n] * sc[2*p  ] + sh[2*p  ];
            float v1 = x[base + (size_t)(2*p+1)*NTOK + n] * sc[2*p+1] + sh[2*p+1];
            hp[p] = pk2(__float2half_rn(v0), __float2half_rn(v1));
        }
        size_t off = ((size_t)(b*NTOK + n)) * CHN + g*8;
        *(uint4*)(g_xn + off) = make_uint4(hp[0], hp[1], hp[2], hp[3]);
    }
}

// ------------------------------------------------------------------
__global__ __launch_bounds__(256) void prep_w(const float* __restrict__ qkvw,
                                              const float* __restrict__ outw) {
    int idx = blockIdx.x * 256 + threadIdx.x;
    #pragma unroll
    for (int r = 0; r < 3; r++) {
        int i = idx + r * 65536;
        g_wq[i] = __float2half_rn(qkvw[i]);
    }
    g_wo[idx] = __float2half_rn(outw[idx]);
}

// ------------------------------------------------------------------
__global__ __launch_bounds__(256) void rsum_reduce() {
    int row = blockIdx.x * 256 + threadIdx.x;
    const float4* p = (const float4*)(g_rsum + (size_t)row * 32);
    float s = 0.f;
    #pragma unroll
    for (int i = 0; i < 8; i++) {
        float4 f = p[i];
        s += f.x + f.y + f.z + f.w;
    }
    g_rinv[row] = 1.f / s;
}

// ==================================================================
// int8 scores kernel: 4 warps, 128x128 tile, warp 64x64
// m16n8k32 s8 MMA (half the instructions), double-sync mainloop,
// direct-register dequant+ex2 epilogue
// ==================================================================
__global__ __launch_bounds__(128, 3)
void scores_gemm() {
    extern __shared__ char smem[];
    float* rbuf = (float*)smem;            // epilogue reuse
    const uint32_t sbase = smem_u32(smem);

    const int tid  = threadIdx.x;
    const int lane = tid & 31;
    const int wid  = tid >> 5;
    const int warp_m = wid & 1;
    const int warp_n = wid >> 1;
    const int b = blockIdx.z;

    const int m0 = blockIdx.x * 128, n0 = blockIdx.y * 128;
    const int8_t* A = g_qi + ((size_t)(b*NTOK + n0)) * CHN;
    const int8_t* B = g_ki + ((size_t)(b*NTOK + m0)) * CHN;
    const int total = CHN / 32;            // 8 chunks of K=32 bytes

    int32_t acc[4][8][4];
    #pragma unroll
    for (int i = 0; i < 4; i++)
        #pragma unroll
        for (int j = 0; j < 8; j++)
            #pragma unroll
            for (int q = 0; q < 4; q++) acc[i][j][q] = 0;

    // prefetch: thread owns row tid of A and row tid of B; 2 x 16B each
    auto prefetch = [&](int cc, int s) {
        if (cc >= total) return;
        int kk = cc * 32;
        uint32_t dA = sbase + s * STAGE8 + tid * TP8;
        uint32_t dB = dA + 6144;
        cpasync16(dA,      A + (size_t)tid * CHN + kk);
        cpasync16(dA + 16, A + (size_t)tid * CHN + kk + 16);
        cpasync16(dB,      B + (size_t)tid * CHN + kk);
        cpasync16(dB + 16, B + (size_t)tid * CHN + kk + 16);
    };

    prefetch(0, 0); CP_COMMIT();
    prefetch(1, 1); CP_COMMIT();
    prefetch(2, 2); CP_COMMIT();

    int s = 0;
    for (int cc = 0; cc < total; cc++) {
        CP_WAIT2();
        __syncthreads();
        const uint32_t tA = sbase + s * STAGE8;
        const uint32_t tB = tA + 6144;
        uint32_t a[4][4];
        #pragma unroll
        for (int mi = 0; mi < 4; mi++) {
            uint32_t addr = tA + (warp_m*64 + mi*16 + (lane & 15)) * TP8
                               + (lane >> 4) * 16;
            ldsm_x4(a[mi][0], a[mi][1], a[mi][2], a[mi][3], addr);
        }
        #pragma unroll
        for (int ni = 0; ni < 4; ni++) {
            uint32_t b0, b1, b2, b3;
            uint32_t addr = tB + (warp_n*64 + ni*16 + (lane & 15)) * TP8
                               + (lane >> 4) * 16;
            ldsm_x4(b0, b1, b2, b3, addr);
            #pragma unroll
            for (int mi = 0; mi < 4; mi++) {
                mma_s8(acc[mi][2*ni],   a[mi][0], a[mi][1], a[mi][2], a[mi][3], b0, b2);
                mma_s8(acc[mi][2*ni+1], a[mi][0], a[mi][1], a[mi][2], a[mi][3], b1, b3);
            }
        }
        __syncthreads();
        prefetch(cc + 3, s);
        CP_COMMIT();
        s = (s == 2) ? 0 : s + 1;
    }
    CP_WAIT0();
    __syncthreads();   // mainloop smem dead

    // ---- direct-register epilogue: dequant + exp + stores + shfl sums ----
    h16* Sb = g_s + (size_t)b*NTOK*NTOK + (size_t)n0*NTOK + m0;
    const int rq = lane >> 2;
    const int cq = (lane & 3) * 2;
    #pragma unroll
    for (int mi = 0; mi < 4; mi++) {
        int rA = warp_m*64 + mi*16 + rq;
        int rB = rA + 8;
        float sumA = 0.f, sumB = 0.f;
        #pragma unroll
        for (int nj = 0; nj < 8; nj++) {
            int c = warp_n*64 + nj*8 + cq;
            uint32_t eA = ex2_h2((float)acc[mi][nj][0]*SCL + EC2,
                                 (float)acc[mi][nj][1]*SCL + EC2);
            uint32_t eB = ex2_h2((float)acc[mi][nj][2]*SCL + EC2,
                                 (float)acc[mi][nj][3]*SCL + EC2);
            *(uint32_t*)(Sb + (size_t)rA*NTOK + c) = eA;
            *(uint32_t*)(Sb + (size_t)rB*NTOK + c) = eB;
            float2 fA = __half22float2(*reinterpret_cast<__half2*>(&eA));
            float2 fB = __half22float2(*reinterpret_cast<__half2*>(&eB));
            sumA += fA.x + fA.y;
            sumB += fB.x + fB.y;
        }
        sumA += __shfl_xor_sync(0xffffffffu, sumA, 1);
        sumA += __shfl_xor_sync(0xffffffffu, sumA, 2);
        sumB += __shfl_xor_sync(0xffffffffu, sumB, 1);
        sumB += __shfl_xor_sync(0xffffffffu, sumB, 2);
        if ((lane & 3) == 0) {
            rbuf[rA*2 + warp_n] = sumA;
            rbuf[rB*2 + warp_n] = sumB;
        }
    }
    __syncthreads();
    if (tid < 128) {
        float rsum = rbuf[tid*2] + rbuf[tid*2 + 1];
        g_rsum[((size_t)b*NTOK + n0 + tid)*32 + blockIdx.x] = rsum;
    }
}

// ==================================================================
// 8-warp fp16 GEMM (256 thr, 128x128 tile, warp 32x64, single-sync loop)
// MODE 0 = QKV (Q/K -> int8, V -> fp16), MODE 2 = AV, MODE 3 = proj
// ==================================================================
template<int MODE>
__global__ __launch_bounds__(256, 2)
void tc_gemm_w8(const float* __restrict__ bias,
                const float* __restrict__ resid,
                float* __restrict__ outf) {
    extern __shared__ char smem[];
    float* stg = (float*)smem;
    const uint32_t sbase = smem_u32(smem);

    const int tid  = threadIdx.x;
    const int lane = tid & 31;
    const int wid  = tid >> 5;
    const int warp_m = wid & 3;
    const int warp_n = wid >> 2;
    const int b = blockIdx.z;

    const h16 *A, *B;
    int lda, ldb;
    int n0 = 0, m0 = 0, c0 = 0;
    if (MODE == 0) {
        n0 = blockIdx.x * 128; m0 = blockIdx.y * 128;
        A = g_wq + (size_t)m0 * CHN;
        B = g_xn + ((size_t)(b*NTOK + n0)) * CHN;
        lda = CHN; ldb = CHN;
    } else if (MODE == 2) {
        c0 = blockIdx.x * 128; n0 = blockIdx.y * 128;
        A = g_s + ((size_t)b*NTOK + n0) * NTOK;
        B = g_v + ((size_t)(b*CHN + c0)) * NTOK;
        lda = NTOK; ldb = NTOK;
    } else {
        n0 = blockIdx.x * 128; m0 = blockIdx.y * 128;
        A = g_wo + (size_t)m0 * CHN;
        B = g_ao + ((size_t)(b*NTOK + n0)) * CHN;
        lda = CHN; ldb = CHN;
    }
    const int Ktot = (MODE == 2) ? NTOK : CHN;
    const int total = Ktot / 32;

    float acc[2][8][4];
    #pragma unroll
    for (int i = 0; i < 2; i++)
        #pragma unroll
        for (int j = 0; j < 8; j++)
            #pragma unroll
            for (int q = 0; q < 4; q++) acc[i][j][q] = 0.f;

    auto prefetch = [&](int cc, int s) {
        if (cc >= total) return;
        int kk = cc * 32;
        uint32_t dA = sbase + s * STAGE_BYTES;
        uint32_t dB = dA + 10240;
        #pragma unroll
        for (int i = 0; i < 2; i++) {
            int lin = tid + 256 * i;
            int row = lin >> 2;
            int col = (lin & 3) * 8;
            cpasync16(dA + (row * TPAD + col) * 2, A + (size_t)row * lda + kk + col);
            cpasync16(dB + (row * TPAD + col) * 2, B + (size_t)row * ldb + kk + col);
        }
    };

    prefetch(0, 0); CP_COMMIT();
    prefetch(1, 1); CP_COMMIT();

    int s = 0, ps = 2;
    for (int cc = 0; cc < total; cc++) {
        CP_WAIT1();
        __syncthreads();
        prefetch(cc + 2, ps); CP_COMMIT();
        const uint32_t tA = sbase + s * STAGE_BYTES;
        const uint32_t tB = tA + 10240;
        #pragma unroll
        for (int ks = 0; ks < 2; ks++) {
            uint32_t a[2][4];
            #pragma unroll
            for (int mi = 0; mi < 2; mi++) {
                uint32_t addr = tA + ((warp_m*32 + mi*16 + (lane & 15)) * TPAD
                                      + ks*16 + (lane >> 4) * 8) * 2;
                ldsm_x4(a[mi][0], a[mi][1], a[mi][2], a[mi][3], addr);
            }
            #pragma unroll
            for (int ni = 0; ni < 4; ni++) {
                uint32_t b0, b1, b2, b3;
                uint32_t addr = tB + ((warp_n*64 + ni*16 + (lane & 15)) * TPAD
                                      + ks*16 + (lane >> 4) * 8) * 2;
                ldsm_x4(b0, b1, b2, b3, addr);
                #pragma unroll
                for (int mi = 0; mi < 2; mi++) {
                    mma_f16(acc[mi][2*ni],   a[mi][0], a[mi][1], a[mi][2], a[mi][3], b0, b2);
                    mma_f16(acc[mi][2*ni+1], a[mi][0], a[mi][1], a[mi][2], a[mi][3], b1, b3);
                }
            }
        }
        s  = (s  == 2) ? 0 : s  + 1;
        ps = (ps == 2) ? 0 : ps + 1;
    }
    CP_WAIT0();
    __syncthreads();

    const int rq = lane >> 2;
    const int cq = (lane & 3) * 2;

    if (MODE == 2) {
        // ---- direct: normalize fragments -> g_ao half2 stores ----
        h16* AOb = g_ao + ((size_t)(b*NTOK + n0)) * CHN + c0;
        const float* rinv = g_rinv + (size_t)b*NTOK + n0;
        #pragma unroll
        for (int mi = 0; mi < 2; mi++) {
            int rA = warp_m*32 + mi*16 + rq;
            int rB = rA + 8;
            float iA = rinv[rA], iB = rinv[rB];
            #pragma unroll
            for (int nj = 0; nj < 8; nj++) {
                int c = warp_n*64 + nj*8 + cq;
                *(uint32_t*)(AOb + (size_t)rA*CHN + c) =
                    pk2(__float2half_rn(acc[mi][nj][0]*iA), __float2half_rn(acc[mi][nj][1]*iA));
                *(uint32_t*)(AOb + (size_t)rB*CHN + c) =
                    pk2(__float2half_rn(acc[mi][nj][2]*iB), __float2half_rn(acc[mi][nj][3]*iB));
            }
        }
    } else if (MODE == 3) {
        // ---- direct: + bias + residual -> fp32 out ----
        #pragma unroll
        for (int mi = 0; mi < 2; mi++) {
            int rA = m0 + warp_m*32 + mi*16 + rq;
            int rB = rA + 8;
            float bA = bias[rA], bB = bias[rB];
            #pragma unroll
            for (int nj = 0; nj < 8; nj++) {
                int c = n0 + warp_n*64 + nj*8 + cq;
                size_t oA = ((size_t)(b*CHN + rA))*NTOK + c;
                size_t oB = ((size_t)(b*CHN + rB))*NTOK + c;
                float2 rrA = *(const float2*)(resid + oA);
                float2 rrB = *(const float2*)(resid + oB);
                *(float2*)(outf + oA) = make_float2(acc[mi][nj][0] + bA + rrA.x,
                                                    acc[mi][nj][1] + bA + rrA.y);
                *(float2*)(outf + oB) = make_float2(acc[mi][nj][2] + bB + rrB.x,
                                                    acc[mi][nj][3] + bB + rrB.y);
            }
        }
    } else {
        // ---- MODE 0: staged epilogue ----
        #pragma unroll
        for (int mi = 0; mi < 2; mi++) {
            #pragma unroll
            for (int nj = 0; nj < 8; nj++) {
                int r = warp_m*32 + mi*16 + rq;
                int c = warp_n*64 + nj*8 + cq;
                *(float2*)&stg[r * SPAD + c]       = make_float2(acc[mi][nj][0], acc[mi][nj][1]);
                *(float2*)&stg[(r + 8) * SPAD + c] = make_float2(acc[mi][nj][2], acc[mi][nj][3]);
            }
        }
        __syncthreads();

        const int r  = tid >> 1;
        const int cb = (tid & 1) * 64;
        if (m0 >= 512) {   // V rows: [c][m] + bias, fp16
            float bb = bias[m0 + r];
            h16* Hr = g_v + ((size_t)(b*CHN + m0 - 512 + r)) * NTOK + n0 + cb;
            #pragma unroll
            for (int j0 = 0; j0 < 64; j0 += 8) {
                uint32_t h4[4];
                #pragma unroll
                for (int p = 0; p < 4; p++)
                    h4[p] = pk2(__float2half_rn(stg[r*SPAD + cb + j0 + 2*p]     + bb),
                                __float2half_rn(stg[r*SPAD + cb + j0 + 2*p + 1] + bb));
                *(uint4*)(Hr + j0) = make_uint4(h4[0],h4[1],h4[2],h4[3]);
            }
        } else {           // Q / K: transpose to [n][c] + bias -> int8
            int8_t* dst = ((m0 < 256) ? g_qi : g_ki) + ((size_t)b*NTOK) * CHN;
            int obase = m0 & 255;
            #pragma unroll
            for (int it = 0; it < 8; it++) {
                int lin = tid + it * 256;
                int j  = lin >> 4;      // token col 0..127
                int ck = lin & 15;      // 8-channel chunk
                float v[8];
                #pragma unroll
                for (int p = 0; p < 8; p++)
                    v[p] = stg[(ck*8 + p) * SPAD + j] + bias[m0 + ck*8 + p];
                uint2 pkd;
                pkd.x = q8(v[0], v[1], v[2], v[3]);
                pkd.y = q8(v[4], v[5], v[6], v[7]);
                size_t off = ((size_t)(n0 + j)) * CHN + obase + ck*8;
                *(uint2*)(dst + off) = pkd;
            }
        }
    }
}

// ------------------------------------------------------------------
extern "C" void kernel_launch(void* const* d_in, const int* in_sizes, int n_in,
                              void* d_out, int out_size) {
    const float* x    = (const float*)d_in[0];
    const float* gnw  = (const float*)d_in[1];
    const float* gnb  = (const float*)d_in[2];
    const float* qkvw = (const float*)d_in[3];
    const float* qkvb = (const float*)d_in[4];
    const float* ow   = (const float*)d_in[5];
    const float* ob   = (const float*)d_in[6];
    float* y = (float*)d_out;

    cudaFuncSetAttribute(tc_gemm_w8<0>, cudaFuncAttributeMaxDynamicSharedMemorySize, SMEM_BYTES);
    cudaFuncSetAttribute(scores_gemm,   cudaFuncAttributeMaxDynamicSharedMemorySize, SMEM_I8);
    cudaFuncSetAttribute(tc_gemm_w8<2>, cudaFuncAttributeMaxDynamicSharedMemorySize, SMEM_BYTES);
    cudaFuncSetAttribute(tc_gemm_w8<3>, cudaFuncAttributeMaxDynamicSharedMemorySize, SMEM_BYTES);

    prep_w   <<<256, 256>>>(qkvw, ow);
    gn_kernel<<<BATCH*32, 256>>>(x, gnw, gnb);
    tc_gemm_w8<0><<<dim3(NTOK/128, 6, BATCH), 256, SMEM_BYTES>>>(qkvb, nullptr, nullptr);
    scores_gemm  <<<dim3(NTOK/128, NTOK/128, BATCH), 128, SMEM_I8>>>();
    rsum_reduce  <<<BATCH*NTOK/256, 256>>>();
    tc_gemm_w8<2><<<dim3(CHN/128, NTOK/128, BATCH), 256, SMEM_BYTES>>>(nullptr, nullptr, nullptr);
    tc_gemm_w8<3><<<dim3(NTOK/128, CHN/128, BATCH), 256, SMEM_BYTES>>>(ob, x, y);
}

// round 17
// speedup vs baseline: 1.2672x; 1.2672x over previous
#include <cuda_runtime.h>
#include <cuda_fp16.h>
#include <cstdint>

#define BATCH 4
#define CHN   256
#define NTOK  4096
#define EPS   1e-5f

typedef __half h16;

// ------------------------------------------------------------------
// scratch (__device__ globals; no allocations allowed) — all fp16
// ------------------------------------------------------------------
__device__ h16 g_xn[(size_t)BATCH*NTOK*CHN];     // groupnormed x [b][n][c]
__device__ h16 g_q [(size_t)BATCH*NTOK*CHN];     // Q [b][n][c]
__device__ h16 g_k [(size_t)BATCH*NTOK*CHN];     // K [b][m][c]
__device__ h16 g_v [(size_t)BATCH*CHN*NTOK];     // V [b][c][m]
__device__ h16 g_s [(size_t)BATCH*NTOK*NTOK];    // exp-scores fp16 [b][n][m]
__device__ h16 g_ao[(size_t)BATCH*NTOK*CHN];     // attn-out (normalized) [b][n][c]
__device__ float g_rsum[(size_t)BATCH*NTOK*32];  // per-key-block row sums
__device__ float g_rinv[(size_t)BATCH*NTOK];     // 1 / total row sum
__device__ h16 g_wq[3*CHN*CHN];
__device__ h16 g_wo[CHN*CHN];

// ------------------------------------------------------------------
__device__ __forceinline__ uint32_t smem_u32(const void* p) {
    uint32_t a;
    asm("{ .reg .u64 t; cvta.to.shared.u64 t, %1; cvt.u32.u64 %0, t; }" : "=r"(a) : "l"(p));
    return a;
}
__device__ __forceinline__ void ldsm_x4(uint32_t& r0, uint32_t& r1, uint32_t& r2,
                                        uint32_t& r3, uint32_t addr) {
    asm volatile("ldmatrix.sync.aligned.m8n8.x4.shared.b16 {%0,%1,%2,%3}, [%4];"
                 : "=r"(r0), "=r"(r1), "=r"(r2), "=r"(r3) : "r"(addr));
}
__device__ __forceinline__ void mma_f16(float* c, uint32_t a0, uint32_t a1,
                                        uint32_t a2, uint32_t a3,
                                        uint32_t b0, uint32_t b1) {
    asm volatile("mma.sync.aligned.m16n8k16.row.col.f32.f16.f16.f32 "
                 "{%0,%1,%2,%3}, {%4,%5,%6,%7}, {%8,%9}, {%0,%1,%2,%3};"
                 : "+f"(c[0]), "+f"(c[1]), "+f"(c[2]), "+f"(c[3])
                 : "r"(a0), "r"(a1), "r"(a2), "r"(a3), "r"(b0), "r"(b1));
}
__device__ __forceinline__ void cpasync16(uint32_t dst, const void* src) {
    asm volatile("cp.async.cg.shared.global [%0], [%1], 16;" :: "r"(dst), "l"(src));
}
#define CP_COMMIT() asm volatile("cp.async.commit_group;" ::: "memory")
#define CP_WAIT2()  asm volatile("cp.async.wait_group 2;" ::: "memory")
#define CP_WAIT1()  asm volatile("cp.async.wait_group 1;" ::: "memory")
#define CP_WAIT0()  asm volatile("cp.async.wait_group 0;" ::: "memory")

__device__ __forceinline__ uint32_t pk2(h16 a, h16 b) {
    __half2 t; t.x = a; t.y = b;
    return *reinterpret_cast<uint32_t*>(&t);
}
__device__ __forceinline__ uint32_t ex2_h2(float t0, float t1) {
    __half2 h = __floats2half2_rn(t0, t1);
    uint32_t in = *reinterpret_cast<uint32_t*>(&h), out;
    asm("ex2.approx.f16x2 %0, %1;" : "=r"(out) : "r"(in));
    return out;
}

// SMEM: 3 stages x (A[128][40] + B[128][40]) h16 = 61440 B, union with
// epilogue stg fp32 [128][132] = 67584 B
#define TPAD 40
#define SPAD 132
#define STAGE_BYTES 20480
#define SMEM_BYTES  (128 * SPAD * 4)   // 67584

// exp(s/16 - 6) = 2^(s*EC1 + EC2)
#define EC1 0.09016844005556021f
#define EC2 -8.65617024533378f

// ------------------------------------------------------------------
// GroupNorm -> fp16 token-major [b][n][c]
// ------------------------------------------------------------------
__global__ __launch_bounds__(256) void gn_kernel(const float* __restrict__ x,
                                                 const float* __restrict__ w,
                                                 const float* __restrict__ bias) {
    int b = blockIdx.x >> 5;
    int g = blockIdx.x & 31;
    size_t base = ((size_t)b * CHN + g * 8) * NTOK;
    const float4* xv = (const float4*)(x + base);
    const int NV = 8 * NTOK / 4;

    float s = 0.f, ss = 0.f;
    for (int i = threadIdx.x; i < NV; i += 256) {
        float4 v = xv[i];
        s  += v.x + v.y + v.z + v.w;
        ss += v.x*v.x + v.y*v.y + v.z*v.z + v.w*v.w;
    }
    __shared__ float rs[256], rss[256];
    rs[threadIdx.x] = s; rss[threadIdx.x] = ss;
    __syncthreads();
    for (int st = 128; st > 0; st >>= 1) {
        if (threadIdx.x < st) { rs[threadIdx.x] += rs[threadIdx.x+st]; rss[threadIdx.x] += rss[threadIdx.x+st]; }
        __syncthreads();
    }
    float mean = rs[0] * (1.f/32768.f);
    float var  = rss[0] * (1.f/32768.f) - mean*mean;
    float rstd = rsqrtf(var + EPS);

    float sc[8], sh[8];
    #pragma unroll
    for (int c = 0; c < 8; c++) {
        sc[c] = w[g*8+c] * rstd;
        sh[c] = bias[g*8+c] - mean * sc[c];
    }
    for (int it = 0; it < 16; it++) {
        int n = it * 256 + threadIdx.x;
        uint32_t hp[4];
        #pragma unroll
        for (int p = 0; p < 4; p++) {
            float v0 = x[base + (size_t)(2*p  )*NTOK + n] * sc[2*p  ] + sh[2*p  ];
            float v1 = x[base + (size_t)(2*p+1)*NTOK + n] * sc[2*p+1] + sh[2*p+1];
            hp[p] = pk2(__float2half_rn(v0), __float2half_rn(v1));
        }
        size_t off = ((size_t)(b*NTOK + n)) * CHN + g*8;
        *(uint4*)(g_xn + off) = make_uint4(hp[0], hp[1], hp[2], hp[3]);
    }
}

// ------------------------------------------------------------------
__global__ __launch_bounds__(256) void prep_w(const float* __restrict__ qkvw,
                                              const float* __restrict__ outw) {
    int idx = blockIdx.x * 256 + threadIdx.x;
    #pragma unroll
    for (int r = 0; r < 3; r++) {
        int i = idx + r * 65536;
        g_wq[i] = __float2half_rn(qkvw[i]);
    }
    g_wo[idx] = __float2half_rn(outw[idx]);
}

// ------------------------------------------------------------------
__global__ __launch_bounds__(256) void rsum_reduce() {
    int row = blockIdx.x * 256 + threadIdx.x;
    const float4* p = (const float4*)(g_rsum + (size_t)row * 32);
    float s = 0.f;
    #pragma unroll
    for (int i = 0; i < 8; i++) {
        float4 f = p[i];
        s += f.x + f.y + f.z + f.w;
    }
    g_rinv[row] = 1.f / s;
}

// ==================================================================
// scores kernel: 4 warps, 128x128 tile, warp 64x64
// double-sync mainloop (hoisted ldsm offsets) + direct ex2 epilogue
// ==================================================================
__global__ __launch_bounds__(128, 3)
void scores_gemm() {
    extern __shared__ char smem[];
    float* rbuf = (float*)smem;
    const uint32_t sbase = smem_u32(smem);

    const int tid  = threadIdx.x;
    const int lane = tid & 31;
    const int wid  = tid >> 5;
    const int warp_m = wid & 1;
    const int warp_n = wid >> 1;
    const int b = blockIdx.z;

    const int m0 = blockIdx.x * 128, n0 = blockIdx.y * 128;
    const h16* A = g_q + ((size_t)(b*NTOK + n0)) * CHN;
    const h16* B = g_k + ((size_t)(b*NTOK + m0)) * CHN;
    const int total = CHN / 32;

    float acc[4][8][4];
    #pragma unroll
    for (int i = 0; i < 4; i++)
        #pragma unroll
        for (int j = 0; j < 8; j++)
            #pragma unroll
            for (int q = 0; q < 4; q++) acc[i][j][q] = 0.f;

    // hoisted ldsm offsets (stage-invariant)
    uint32_t offA[4], offB[4];
    #pragma unroll
    for (int mi = 0; mi < 4; mi++)
        offA[mi] = ((warp_m*64 + mi*16 + (lane & 15)) * TPAD + (lane >> 4) * 8) * 2;
    #pragma unroll
    for (int ni = 0; ni < 4; ni++)
        offB[ni] = ((warp_n*64 + ni*16 + (lane & 15)) * TPAD + (lane >> 4) * 8) * 2 + 10240;

    const int prow = tid >> 2;
    const int pcol = (tid & 3) * 8;

    auto prefetch = [&](int cc, int s) {
        if (cc >= total) return;
        int kk = cc * 32;
        uint32_t dA = sbase + s * STAGE_BYTES;
        uint32_t dB = dA + 10240;
        #pragma unroll
        for (int i = 0; i < 4; i++) {
            int row = prow + 32 * i;
            cpasync16(dA + (row * TPAD + pcol) * 2, A + (size_t)row * CHN + kk + pcol);
            cpasync16(dB + (row * TPAD + pcol) * 2, B + (size_t)row * CHN + kk + pcol);
        }
    };

    prefetch(0, 0); CP_COMMIT();
    prefetch(1, 1); CP_COMMIT();
    prefetch(2, 2); CP_COMMIT();

    int s = 0;
    for (int cc = 0; cc < total; cc++) {
        CP_WAIT2();
        __syncthreads();
        const uint32_t tS = sbase + s * STAGE_BYTES;
        #pragma unroll
        for (int ks = 0; ks < 2; ks++) {
            uint32_t a[4][4];
            #pragma unroll
            for (int mi = 0; mi < 4; mi++)
                ldsm_x4(a[mi][0], a[mi][1], a[mi][2], a[mi][3], tS + offA[mi] + ks*32);
            #pragma unroll
            for (int ni = 0; ni < 4; ni++) {
                uint32_t b0, b1, b2, b3;
                ldsm_x4(b0, b1, b2, b3, tS + offB[ni] + ks*32);
                #pragma unroll
                for (int mi = 0; mi < 4; mi++) {
                    mma_f16(acc[mi][2*ni],   a[mi][0], a[mi][1], a[mi][2], a[mi][3], b0, b2);
                    mma_f16(acc[mi][2*ni+1], a[mi][0], a[mi][1], a[mi][2], a[mi][3], b1, b3);
                }
            }
        }
        __syncthreads();
        prefetch(cc + 3, s);
        CP_COMMIT();
        s = (s == 2) ? 0 : s + 1;
    }
    CP_WAIT0();
    __syncthreads();   // mainloop smem dead

    // ---- direct-register epilogue: exp + 32-bit stores + shfl row sums ----
    h16* Sb = g_s + (size_t)b*NTOK*NTOK + (size_t)n0*NTOK + m0;
    const int rq = lane >> 2;
    const int cq = (lane & 3) * 2;
    #pragma unroll
    for (int mi = 0; mi < 4; mi++) {
        int rA = warp_m*64 + mi*16 + rq;
        int rB = rA + 8;
        float sumA = 0.f, sumB = 0.f;
        #pragma unroll
        for (int nj = 0; nj < 8; nj++) {
            int c = warp_n*64 + nj*8 + cq;
            uint32_t eA = ex2_h2(acc[mi][nj][0]*EC1 + EC2, acc[mi][nj][1]*EC1 + EC2);
            uint32_t eB = ex2_h2(acc[mi][nj][2]*EC1 + EC2, acc[mi][nj][3]*EC1 + EC2);
            *(uint32_t*)(Sb + (size_t)rA*NTOK + c) = eA;
            *(uint32_t*)(Sb + (size_t)rB*NTOK + c) = eB;
            float2 fA = __half22float2(*reinterpret_cast<__half2*>(&eA));
            float2 fB = __half22float2(*reinterpret_cast<__half2*>(&eB));
            sumA += fA.x + fA.y;
            sumB += fB.x + fB.y;
        }
        sumA += __shfl_xor_sync(0xffffffffu, sumA, 1);
        sumA += __shfl_xor_sync(0xffffffffu, sumA, 2);
        sumB += __shfl_xor_sync(0xffffffffu, sumB, 1);
        sumB += __shfl_xor_sync(0xffffffffu, sumB, 2);
        if ((lane & 3) == 0) {
            rbuf[rA*2 + warp_n] = sumA;
            rbuf[rB*2 + warp_n] = sumB;
        }
    }
    __syncthreads();
    if (tid < 128) {
        float rsum = rbuf[tid*2] + rbuf[tid*2 + 1];
        g_rsum[((size_t)b*NTOK + n0 + tid)*32 + blockIdx.x] = rsum;
    }
}

// ==================================================================
// 8-warp GEMM (256 thr, 128x128 tile, warp 32x64, single-sync loop,
// hoisted ldsm offsets)
// MODE 0 = QKV (staged), MODE 2 = AV (direct), MODE 3 = proj (direct)
// ==================================================================
template<int MODE>
__global__ __launch_bounds__(256, 2)
void tc_gemm_w8(const float* __restrict__ bias,
                const float* __restrict__ resid,
                float* __restrict__ outf) {
    extern __shared__ char smem[];
    float* stg = (float*)smem;
    const uint32_t sbase = smem_u32(smem);

    const int tid  = threadIdx.x;
    const int lane = tid & 31;
    const int wid  = tid >> 5;
    const int warp_m = wid & 3;
    const int warp_n = wid >> 2;
    const int b = blockIdx.z;

    const h16 *A, *B;
    int lda, ldb;
    int n0 = 0, m0 = 0, c0 = 0;
    if (MODE == 0) {
        n0 = blockIdx.x * 128; m0 = blockIdx.y * 128;
        A = g_wq + (size_t)m0 * CHN;
        B = g_xn + ((size_t)(b*NTOK + n0)) * CHN;
        lda = CHN; ldb = CHN;
    } else if (MODE == 2) {
        c0 = blockIdx.x * 128; n0 = blockIdx.y * 128;
        A = g_s + ((size_t)b*NTOK + n0) * NTOK;
        B = g_v + ((size_t)(b*CHN + c0)) * NTOK;
        lda = NTOK; ldb = NTOK;
    } else {
        n0 = blockIdx.x * 128; m0 = blockIdx.y * 128;
        A = g_wo + (size_t)m0 * CHN;
        B = g_ao + ((size_t)(b*NTOK + n0)) * CHN;
        lda = CHN; ldb = CHN;
    }
    const int Ktot = (MODE == 2) ? NTOK : CHN;
    const int total = Ktot / 32;

    float acc[2][8][4];
    #pragma unroll
    for (int i = 0; i < 2; i++)
        #pragma unroll
        for (int j = 0; j < 8; j++)
            #pragma unroll
            for (int q = 0; q < 4; q++) acc[i][j][q] = 0.f;

    uint32_t offA[2], offB[4];
    #pragma unroll
    for (int mi = 0; mi < 2; mi++)
        offA[mi] = ((warp_m*32 + mi*16 + (lane & 15)) * TPAD + (lane >> 4) * 8) * 2;
    #pragma unroll
    for (int ni = 0; ni < 4; ni++)
        offB[ni] = ((warp_n*64 + ni*16 + (lane & 15)) * TPAD + (lane >> 4) * 8) * 2 + 10240;

    auto prefetch = [&](int cc, int s) {
        if (cc >= total) return;
        int kk = cc * 32;
        uint32_t dA = sbase + s * STAGE_BYTES;
        uint32_t dB = dA + 10240;
        #pragma unroll
        for (int i = 0; i < 2; i++) {
            int lin = tid + 256 * i;
            int row = lin >> 2;
            int col = (lin & 3) * 8;
            cpasync16(dA + (row * TPAD + col) * 2, A + (size_t)row * lda + kk + col);
            cpasync16(dB + (row * TPAD + col) * 2, B + (size_t)row * ldb + kk + col);
        }
    };

    prefetch(0, 0); CP_COMMIT();
    prefetch(1, 1); CP_COMMIT();

    int s = 0, ps = 2;
    for (int cc = 0; cc < total; cc++) {
        CP_WAIT1();
        __syncthreads();
        prefetch(cc + 2, ps); CP_COMMIT();
        const uint32_t tS = sbase + s * STAGE_BYTES;
        #pragma unroll
        for (int ks = 0; ks < 2; ks++) {
            uint32_t a[2][4];
            #pragma unroll
            for (int mi = 0; mi < 2; mi++)
                ldsm_x4(a[mi][0], a[mi][1], a[mi][2], a[mi][3], tS + offA[mi] + ks*32);
            #pragma unroll
            for (int ni = 0; ni < 4; ni++) {
                uint32_t b0, b1, b2, b3;
                ldsm_x4(b0, b1, b2, b3, tS + offB[ni] + ks*32);
                #pragma unroll
                for (int mi = 0; mi < 2; mi++) {
                    mma_f16(acc[mi][2*ni],   a[mi][0], a[mi][1], a[mi][2], a[mi][3], b0, b2);
                    mma_f16(acc[mi][2*ni+1], a[mi][0], a[mi][1], a[mi][2], a[mi][3], b1, b3);
                }
            }
        }
        s  = (s  == 2) ? 0 : s  + 1;
        ps = (ps == 2) ? 0 : ps + 1;
    }
    CP_WAIT0();
    __syncthreads();

    const int rq = lane >> 2;
    const int cq = (lane & 3) * 2;

    if (MODE == 2) {
        h16* AOb = g_ao + ((size_t)(b*NTOK + n0)) * CHN + c0;
        const float* rinv = g_rinv + (size_t)b*NTOK + n0;
        #pragma unroll
        for (int mi = 0; mi < 2; mi++) {
            int rA = warp_m*32 + mi*16 + rq;
            int rB = rA + 8;
            float iA = rinv[rA], iB = rinv[rB];
            #pragma unroll
            for (int nj = 0; nj < 8; nj++) {
                int c = warp_n*64 + nj*8 + cq;
                *(uint32_t*)(AOb + (size_t)rA*CHN + c) =
                    pk2(__float2half_rn(acc[mi][nj][0]*iA), __float2half_rn(acc[mi][nj][1]*iA));
                *(uint32_t*)(AOb + (size_t)rB*CHN + c) =
                    pk2(__float2half_rn(acc[mi][nj][2]*iB), __float2half_rn(acc[mi][nj][3]*iB));
            }
        }
    } else if (MODE == 3) {
        #pragma unroll
        for (int mi = 0; mi < 2; mi++) {
            int rA = m0 + warp_m*32 + mi*16 + rq;
            int rB = rA + 8;
            float bA = bias[rA], bB = bias[rB];
            #pragma unroll
            for (int nj = 0; nj < 8; nj++) {
                int c = n0 + warp_n*64 + nj*8 + cq;
                size_t oA = ((size_t)(b*CHN + rA))*NTOK + c;
                size_t oB = ((size_t)(b*CHN + rB))*NTOK + c;
                float2 rrA = *(const float2*)(resid + oA);
                float2 rrB = *(const float2*)(resid + oB);
                *(float2*)(outf + oA) = make_float2(acc[mi][nj][0] + bA + rrA.x,
                                                    acc[mi][nj][1] + bA + rrA.y);
                *(float2*)(outf + oB) = make_float2(acc[mi][nj][2] + bB + rrB.x,
                                                    acc[mi][nj][3] + bB + rrB.y);
            }
        }
    } else {
        #pragma unroll
        for (int mi = 0; mi < 2; mi++) {
            #pragma unroll
            for (int nj = 0; nj < 8; nj++) {
                int r = warp_m*32 + mi*16 + rq;
                int c = warp_n*64 + nj*8 + cq;
                *(float2*)&stg[r * SPAD + c]       = make_float2(acc[mi][nj][0], acc[mi][nj][1]);
                *(float2*)&stg[(r + 8) * SPAD + c] = make_float2(acc[mi][nj][2], acc[mi][nj][3]);
            }
        }
        __syncthreads();

        const int r  = tid >> 1;
        const int cb = (tid & 1) * 64;
        if (m0 >= 512) {   // V rows: [c][m] + bias
            float bb = bias[m0 + r];
            h16* Hr = g_v + ((size_t)(b*CHN + m0 - 512 + r)) * NTOK + n0 + cb;
            #pragma unroll
            for (int j0 = 0; j0 < 64; j0 += 8) {
                uint32_t h4[4];
                #pragma unroll
                for (int p = 0; p < 4; p++)
                    h4[p] = pk2(__float2half_rn(stg[r*SPAD + cb + j0 + 2*p]     + bb),
                                __float2half_rn(stg[r*SPAD + cb + j0 + 2*p + 1] + bb));
                *(uint4*)(Hr + j0) = make_uint4(h4[0],h4[1],h4[2],h4[3]);
            }
        } else {           // Q / K: transpose to [n][c] + bias
            h16* dst = ((m0 < 256) ? g_q : g_k) + ((size_t)b*NTOK) * CHN;
            int obase = m0 & 255;
            #pragma unroll
            for (int it = 0; it < 8; it++) {
                int lin = tid + it * 256;
                int j  = lin >> 4;
                int ck = lin & 15;
                uint32_t h4[4];
                #pragma unroll
                for (int p = 0; p < 4; p++) {
                    float v0 = stg[(ck*8 + 2*p    ) * SPAD + j] + bias[m0 + ck*8 + 2*p];
                    float v1 = stg[(ck*8 + 2*p + 1) * SPAD + j] + bias[m0 + ck*8 + 2*p + 1];
                    h4[p] = pk2(__float2half_rn(v0), __float2half_rn(v1));
                }
                size_t off = ((size_t)(n0 + j)) * CHN + obase + ck*8;
                *(uint4*)(dst + off) = make_uint4(h4[0],h4[1],h4[2],h4[3]);
            }
        }
    }
}

// ------------------------------------------------------------------
extern "C" void kernel_launch(void* const* d_in, const int* in_sizes, int n_in,
                              void* d_out, int out_size) {
    const float* x    = (const float*)d_in[0];
    const float* gnw  = (const float*)d_in[1];
    const float* gnb  = (const float*)d_in[2];
    const float* qkvw = (const float*)d_in[3];
    const float* qkvb = (const float*)d_in[4];
    const float* ow   = (const float*)d_in[5];
    const float* ob   = (const float*)d_in[6];
    float* y = (float*)d_out;

    cudaFuncSetAttribute(tc_gemm_w8<0>, cudaFuncAttributeMaxDynamicSharedMemorySize, SMEM_BYTES);
    cudaFuncSetAttribute(scores_gemm,   cudaFuncAttributeMaxDynamicSharedMemorySize, SMEM_BYTES);
    cudaFuncSetAttribute(tc_gemm_w8<2>, cudaFuncAttributeMaxDynamicSharedMemorySize, SMEM_BYTES);
    cudaFuncSetAttribute(tc_gemm_w8<3>, cudaFuncAttributeMaxDynamicSharedMemorySize, SMEM_BYTES);

    prep_w   <<<256, 256>>>(qkvw, ow);
    gn_kernel<<<BATCH*32, 256>>>(x, gnw, gnb);
    tc_gemm_w8<0><<<dim3(NTOK/128, 6, BATCH), 256, SMEM_BYTES>>>(qkvb, nullptr, nullptr);
    scores_gemm  <<<dim3(NTOK/128, NTOK/128, BATCH), 128, SMEM_BYTES>>>();
    rsum_reduce  <<<BATCH*NTOK/256, 256>>>();
    tc_gemm_w8<2><<<dim3(CHN/128, NTOK/128, BATCH), 256, SMEM_BYTES>>>(nullptr, nullptr, nullptr);
    tc_gemm_w8<3><<<dim3(NTOK/128, CHN/128, BATCH), 256, SMEM_BYTES>>>(ob, x, y);
}